// round 10
// baseline (speedup 1.0000x reference)
#include <cuda_runtime.h>

// Nosé–Hoover chain (N_CHAIN=2) velocity-Verlet, B=1024, NDOF=64, 200 steps.
// Out: [traj_x (201,1024,64) | traj_v (201,1024,64)] fp32.
//
// R7: two-kernel decoupling (stream-ordered, no flag sync — R6's intra-kernel
// handshake collapsed).
//  K1 nhc_chain: 1024 chains SIMT (1 system/lane, 32 blocks x 32 thr). Closed
//    3-moment recursion -> only sv[step][sys] is emitted (800KB, L2-resident).
//    Path-bound ~56 cyc/step -> ~6-7us.
//  K2 nhc_sweep: chain-free sweep. 2 sys/warp, float4/lane; per step: one
//    broadcast __ldg of sv (batched 4-ahead), scalar coeffs, 8 packed f32x2
//    ops, 2x STG.128. Runs into the LTS store floor (~105MB -> ~9us).
// Both kernels const-specialize kT=mass=Q=1 (uniform branch; general path kept).

namespace {
constexpr int NSYS   = 1024;
constexpr int NSTEP  = 200;
constexpr int F4SYS  = 16;                  // float4 per system
constexpr int F4SNAP = NSYS * F4SYS;        // 16384 float4 per snapshot
}

__device__ float d_sv[NSTEP][NSYS];         // per-step velocity scale factors

#define FMA2(d,a,b,c) asm("fma.rn.f32x2 %0,%1,%2,%3;" : "=l"(d) : "l"(a), "l"(b), "l"(c))
#define MUL2(d,a,b)   asm("mul.rn.f32x2 %0,%1,%2;"    : "=l"(d) : "l"(a), "l"(b))
#define PACK2(d,f)    asm("mov.b64 %0,{%1,%1};"       : "=l"(d) : "f"(f))
#define PACKAB(d,a,b) asm("mov.b64 %0,{%1,%2;}"       : "=l"(d) : "f"(a), "f"(b))
#undef PACKAB
#define PACKAB(d,a,b) asm("mov.b64 %0,{%1,%2};"       : "=l"(d) : "f"(a), "f"(b))
#define STG128(p,off,a,b) \
    asm volatile("st.global.v2.b64 [%0+" #off "],{%1,%2};" :: "l"(p), "l"(a), "l"(b) : "memory")

// exp(-z) for |z| <= ~3e-4: 1 - z + z^2/2  (rel err ~ z^3/6 <= 5e-12)
__device__ __forceinline__ float expm(float z) {
    return fmaf(fmaf(0.5f, z, -1.0f), z, 1.0f);
}

// ---------------- K1: thermostat chains (1 system per lane) ----------------
__device__ __forceinline__ void chain_loop(float kT, float mass, float Q,
                                           float sxx, float sxv, float svv, int s)
{
    const float dt   = 0.002f;
    const float dt4  = 0.25f  * dt;
    const float dt8  = 0.125f * dt;
    const float dth  = 0.5f   * dt;
    const float invQ = 1.0f / Q;
    const float c1   = dth / mass;
    const float A    = 1.0f - dt * c1;
    const float A2   = A * A;
    const float cx0  = -c1 * (1.0f + A);
    const float mIQ  = mass * invQ;
    const float nkIQ = -64.0f * kT * invQ;
    const float kTiQ = kT * invQ;
    const float m0c  = cx0 * cx0;
    const float m1c  = 2.0f * cx0 * A;
    const float p1c  = 2.0f * A * dt;
    const float p2c  = dt * dt;
    const float acx  = A * cx0;
    const float mc   = A2 + dt * cx0;
    const float dA   = dt * A;

    float xi0 = 0.0f, xi1 = 0.0f;
    float* psv = &d_sv[0][s];

    #pragma unroll 4
    for (int k = 0; k < NSTEP; ++k) {
        float G  = fmaf(mIQ, svv, nkIQ);
        xi1 = fmaf(dt4, G, xi1);
        float G0 = fmaf(xi0, xi0, -kTiQ);
        float z1 = xi1 * dt8;
        float se = expm(z1);
        float s2 = se * se;
        float dt4s = dt4 * se;
        float xi0a = fmaf(xi0, s2, G0 * dt4s);
        float z0 = xi0a * dth;
        float sv  = expm(z0);
        float sv2 = sv * sv;
        float m0 = m0c * sxx;
        float m1 = m1c * sxv;
        float m2 = A2  * svv;
        float svv_n = sv2 * fmaf(sv2, m2, fmaf(sv, m1, m0));
        float G2 = fmaf(mIQ, svv_n, nkIQ);
        xi0 = fmaf(dt4s, G2, xi0a * s2);
        float G3 = fmaf(xi0, xi0, -kTiQ);
        xi1 = fmaf(dt4, G3, xi1);
        float sxx_n = fmaf(p2c * sv2, svv, fmaf(p1c * sv, sxv, A2 * sxx));
        float sxv_n = fmaf((dA * sv) * sv2, svv,
                           fmaf(mc * sv2, sxv, (acx * sv) * sxx));
        sxx = sxx_n; sxv = sxv_n; svv = svv_n;
        *psv = sv;
        psv += NSYS;
    }
}

__global__ __launch_bounds__(32, 1)
void nhc_chain(const float4* __restrict__ gx0,
               const float4* __restrict__ gv0,
               const float*  __restrict__ pkT,
               const float*  __restrict__ pmass,
               const float*  __restrict__ pQ)
{
    const int s = blockIdx.x * 32 + threadIdx.x;     // system id

    const float kT   = *pkT;
    const float mass = *pmass;
    const float Q    = *pQ;

    // initial moments for this lane's system: 16+16 strided float4 loads (MLP)
    float a = 0.0f, c = 0.0f, e = 0.0f;
    const float4* xb = gx0 + s * F4SYS;
    const float4* vb = gv0 + s * F4SYS;
    #pragma unroll
    for (int i = 0; i < F4SYS; ++i) {
        float4 x = xb[i];
        float4 v = vb[i];
        a = fmaf(x.x, x.x, a); a = fmaf(x.y, x.y, a); a = fmaf(x.z, x.z, a); a = fmaf(x.w, x.w, a);
        c = fmaf(x.x, v.x, c); c = fmaf(x.y, v.y, c); c = fmaf(x.z, v.z, c); c = fmaf(x.w, v.w, c);
        e = fmaf(v.x, v.x, e); e = fmaf(v.y, v.y, e); e = fmaf(v.z, v.z, e); e = fmaf(v.w, v.w, e);
    }

    if (kT == 1.0f && mass == 1.0f && Q == 1.0f)
        chain_loop(1.0f, 1.0f, 1.0f, a, c, e, s);
    else
        chain_loop(kT, mass, Q, a, c, e, s);
}

// ---------------- K2: chain-free trajectory sweep ----------------
__device__ __forceinline__ void sweep_loop(float mass, int sys, int lane,
                                           const float4* __restrict__ gx0,
                                           const float4* __restrict__ gv0,
                                           float4* __restrict__ out)
{
    const float dt  = 0.002f;
    const float c1  = 0.5f * dt / mass;
    const float A   = 1.0f - dt * c1;
    const float cx0 = -c1 * (1.0f + A);

    const int idx = sys * F4SYS + (lane & 15);       // float4 slot

    const float4 x0 = gx0[idx];
    const float4 v0 = gv0[idx];

    const float4* px = out + idx;
    const float4* pv = out + (size_t)(NSTEP + 1) * F4SNAP + idx;

    unsigned long long Xp0, Xp1, Vp0, Vp1, Ap;
    PACKAB(Xp0, x0.x, x0.y); PACKAB(Xp1, x0.z, x0.w);
    PACKAB(Vp0, v0.x, v0.y); PACKAB(Vp1, v0.z, v0.w);
    PACK2(Ap, A);

    // snapshot 0
    STG128(px, 0, Xp0, Xp1);
    STG128(pv, 0, Vp0, Vp1);

    const float* psv = &d_sv[0][sys];

    #pragma unroll 1
    for (int grp = 0; grp < NSTEP / 4; ++grp) {
        float svs0 = __ldg(psv);
        float svs1 = __ldg(psv + NSYS);
        float svs2 = __ldg(psv + 2 * NSYS);
        float svs3 = __ldg(psv + 3 * NSYS);
        psv += 4 * NSYS;
        #pragma unroll
        for (int j = 0; j < 4; ++j) {
            float sv  = (j == 0) ? svs0 : (j == 1) ? svs1 : (j == 2) ? svs2 : svs3;
            float sv2 = sv * sv;
            float B   = dt  * sv;
            float Cx  = cx0 * sv;
            float Cv  = A   * sv2;
            unsigned long long Bp, Cxp, Cvp, t0, t1, u0, u1, xn0, xn1, vn0, vn1;
            PACK2(Bp, B); PACK2(Cxp, Cx); PACK2(Cvp, Cv);
            MUL2(t0, Bp,  Vp0);  MUL2(t1, Bp,  Vp1);
            MUL2(u0, Cvp, Vp0);  MUL2(u1, Cvp, Vp1);
            FMA2(xn0, Ap,  Xp0, t0);  FMA2(xn1, Ap,  Xp1, t1);
            FMA2(vn0, Cxp, Xp0, u0);  FMA2(vn1, Cxp, Xp1, u1);
            Xp0 = xn0; Xp1 = xn1; Vp0 = vn0; Vp1 = vn1;
            if (j == 0) { STG128(px, 262144,  Xp0, Xp1); STG128(pv, 262144,  Vp0, Vp1); }
            if (j == 1) { STG128(px, 524288,  Xp0, Xp1); STG128(pv, 524288,  Vp0, Vp1); }
            if (j == 2) { STG128(px, 786432,  Xp0, Xp1); STG128(pv, 786432,  Vp0, Vp1); }
            if (j == 3) { STG128(px, 1048576, Xp0, Xp1); STG128(pv, 1048576, Vp0, Vp1); }
        }
        px += 4 * F4SNAP;
        pv += 4 * F4SNAP;
    }
}

__global__ __launch_bounds__(128, 1)
void nhc_sweep(const float4* __restrict__ gx0,
               const float4* __restrict__ gv0,
               const float*  __restrict__ pmass,
               float4*       __restrict__ out)
{
    const int tid  = threadIdx.x;
    const int lane = tid & 31;
    const int sys  = blockIdx.x * 8 + ((tid >> 4));  // 2 systems per warp

    const float mass = *pmass;

    if (mass == 1.0f)
        sweep_loop(1.0f, sys, lane, gx0, gv0, out);
    else
        sweep_loop(mass, sys, lane, gx0, gv0, out);
}

extern "C" void kernel_launch(void* const* d_in, const int* in_sizes, int n_in,
                              void* d_out, int out_size)
{
    const float4* x0   = (const float4*)d_in[0];
    const float4* v0   = (const float4*)d_in[1];
    const float*  kT   = (const float*)d_in[2];
    const float*  mass = (const float*)d_in[3];
    const float*  Q    = (const float*)d_in[4];
    float4* out = (float4*)d_out;

    // K1: 1024 chains, 1/lane, 32 warps on 32 SMs (path-bound, ~6us)
    nhc_chain<<<32, 32>>>(x0, v0, kT, mass, Q);
    // K2: chain-free sweep, store-floor bound (~9us); stream order = sync
    nhc_sweep<<<128, 128>>>(x0, v0, mass, out);
}

// round 13
// speedup vs baseline: 2.3463x; 2.3463x over previous
#include <cuda_runtime.h>

// Nosé–Hoover chain (N_CHAIN=2) velocity-Verlet, B=1024, NDOF=64, 200 steps.
// Out: [traj_x (201,1024,64) | traj_v (201,1024,64)] fp32.
//
// R11: back to the fused register-resident design (R5 = best), improved:
//  - 4 systems/warp (8 lanes/system, 8 dof/lane as 4 f32x2 regs each for X,V):
//    the SIMT thermostat chain (each lane carries its own system's moments
//    xi0,xi1,Sxx,Sxv,Svv) is amortized over 4 systems -> 256 warps total.
//  - explicit 1-step software pipeline: chain for step k+1 is computed in the
//    same block as the elementwise map + stores of step k (chain depends only
//    on the moments, never the vectors), so its ~70-cycle dependent-FMA path
//    is covered by independent packed ops and STG issue. 201 chain steps
//    (one extra, unused) keeps the loop branch-free.
//  - const-specialized fast path for kT=mass=Q=1 (uniform branch; general
//    path kept for arbitrary scalars).
// Memory hand-offs (R6/R7 split kernels) are abandoned: sv-from-memory gated
// the sweep on L2 round trips per step (issue 5.8%, 47us).

namespace {
constexpr int NSYS   = 1024;
constexpr int NSTEP  = 200;
constexpr int F4SYS  = 16;                  // float4 per system
constexpr int F4SNAP = NSYS * F4SYS;        // 16384 float4 / snapshot (256KB)
}

#define FMA2(d,a,b,c) asm("fma.rn.f32x2 %0,%1,%2,%3;" : "=l"(d) : "l"(a), "l"(b), "l"(c))
#define MUL2(d,a,b)   asm("mul.rn.f32x2 %0,%1,%2;"    : "=l"(d) : "l"(a), "l"(b))
#define PACK2(d,f)    asm("mov.b64 %0,{%1,%1};"       : "=l"(d) : "f"(f))
#define PACKAB(d,a,b) asm("mov.b64 %0,{%1,%2};"       : "=l"(d) : "f"(a), "f"(b))
#define STG128(p,off,a,b) \
    asm volatile("st.global.v2.b64 [%0+" #off "],{%1,%2};" :: "l"(p), "l"(a), "l"(b) : "memory")

// exp(-z) for |z| <= ~3e-4: 1 - z + z^2/2  (rel err ~ z^3/6 <= 5e-12)
__device__ __forceinline__ float expm(float z) {
    return fmaf(fmaf(0.5f, z, -1.0f), z, 1.0f);
}

__device__ __forceinline__ void run_loop(
    float kT, float mass, float Q,
    float sxx, float sxv, float svv,
    unsigned long long X01, unsigned long long X23,
    unsigned long long X45, unsigned long long X67,
    unsigned long long V01, unsigned long long V23,
    unsigned long long V45, unsigned long long V67,
    const float4* px, const float4* pv)          // bases at snapshot 1
{
    const float dt   = 0.002f;
    const float dt4  = 0.25f  * dt;
    const float dt8  = 0.125f * dt;
    const float dth  = 0.5f   * dt;
    const float invQ = 1.0f / Q;
    const float c1   = dth / mass;
    const float A    = 1.0f - dt * c1;
    const float A2   = A * A;
    const float cx0  = -c1 * (1.0f + A);
    const float mIQ  = mass * invQ;
    const float nkIQ = -64.0f * kT * invQ;
    const float kTiQ = kT * invQ;
    const float m0c  = cx0 * cx0;
    const float m1c  = 2.0f * cx0 * A;
    const float p1c  = 2.0f * A * dt;
    const float p2c  = dt * dt;
    const float acx  = A * cx0;
    const float mc   = A2 + dt * cx0;
    const float dA   = dt * A;

    unsigned long long Ap;
    PACK2(Ap, A);

    float xi0 = 0.0f, xi1 = 0.0f;

    // one thermostat step: updates (xi0, xi1, Sxx, Sxv, Svv), returns sv
    auto chain_step = [&]() -> float {
        float G  = fmaf(mIQ, svv, nkIQ);
        xi1 = fmaf(dt4, G, xi1);
        float G0 = fmaf(xi0, xi0, -kTiQ);
        float z1 = xi1 * dt8;
        float se = expm(z1);
        float s2 = se * se;
        float dt4s = dt4 * se;
        float xi0a = fmaf(xi0, s2, G0 * dt4s);
        float z0 = xi0a * dth;
        float sv  = expm(z0);
        float sv2 = sv * sv;
        float svv_n = sv2 * fmaf(sv2, A2 * svv, fmaf(sv, m1c * sxv, m0c * sxx));
        float G2 = fmaf(mIQ, svv_n, nkIQ);
        xi0 = fmaf(dt4s, G2, xi0a * s2);
        float G3 = fmaf(xi0, xi0, -kTiQ);
        xi1 = fmaf(dt4, G3, xi1);
        float sxx_n = fmaf(p2c * sv2, svv, fmaf(p1c * sv, sxv, A2 * sxx));
        float sxv_n = fmaf((dA * sv) * sv2, svv,
                           fmaf(mc * sv2, sxv, (acx * sv) * sxx));
        sxx = sxx_n; sxv = sxv_n; svv = svv_n;
        return sv;
    };

    // software pipeline: sv for step k computed one iteration ahead
    float sv_cur = chain_step();                  // step 0

    for (int k = 0; k < NSTEP; k += 2) {
        #pragma unroll
        for (int u = 0; u < 2; ++u) {
            const float sv = sv_cur;
            sv_cur = chain_step();                // step k+u+1 (last one unused)

            // coefficients for this step's linear map
            float sv2 = sv * sv;
            float B   = dt  * sv;
            float Cx  = cx0 * sv;
            float Cv  = A   * sv2;
            unsigned long long Bp, Cxp, Cvp;
            PACK2(Bp, B); PACK2(Cxp, Cx); PACK2(Cvp, Cv);

            // x' = A x + B v ; v' = Cx x + Cv v   (4 f32x2 pairs)
            unsigned long long t0, t1, t2, t3, u0, u1, u2, u3;
            MUL2(t0, Bp, V01); MUL2(t1, Bp, V23); MUL2(t2, Bp, V45); MUL2(t3, Bp, V67);
            MUL2(u0, Cvp, V01); MUL2(u1, Cvp, V23); MUL2(u2, Cvp, V45); MUL2(u3, Cvp, V67);
            unsigned long long xn0, xn1, xn2, xn3;
            FMA2(xn0, Ap, X01, t0); FMA2(xn1, Ap, X23, t1);
            FMA2(xn2, Ap, X45, t2); FMA2(xn3, Ap, X67, t3);
            unsigned long long vn0, vn1, vn2, vn3;
            FMA2(vn0, Cxp, X01, u0); FMA2(vn1, Cxp, X23, u1);
            FMA2(vn2, Cxp, X45, u2); FMA2(vn3, Cxp, X67, u3);
            X01 = xn0; X23 = xn1; X45 = xn2; X67 = xn3;
            V01 = vn0; V23 = vn1; V45 = vn2; V67 = vn3;

            // snapshot stores: 2x STG.128 for x, 2 for v (imm offsets)
            if (u == 0) {
                STG128(px, 0,      X01, X23);  STG128(px, 128,    X45, X67);
                STG128(pv, 0,      V01, V23);  STG128(pv, 128,    V45, V67);
            } else {
                STG128(px, 262144, X01, X23);  STG128(px, 262272, X45, X67);
                STG128(pv, 262144, V01, V23);  STG128(pv, 262272, V45, V67);
            }
        }
        px += 2 * F4SNAP;
        pv += 2 * F4SNAP;
    }
}

__global__ __launch_bounds__(64, 1)
void nhc_kernel(const float4* __restrict__ gx0,
                const float4* __restrict__ gv0,
                const float*  __restrict__ pkT,
                const float*  __restrict__ pmass,
                const float*  __restrict__ pQ,
                float4*       __restrict__ out)
{
    const int tid  = threadIdx.x;
    const int lane = tid & 31;
    const int w    = tid >> 5;                      // warp in block (0,1)
    const int sys  = (blockIdx.x * 2 + w) * 4 + (lane >> 3);  // 4 sys/warp
    const int ls   = lane & 7;                      // lane-in-system

    const float kT   = *pkT;
    const float mass = *pmass;
    const float Q    = *pQ;

    const int idx = sys * F4SYS + ls;               // float4 slot

    const float4 xa = gx0[idx], xb = gx0[idx + 8];
    const float4 va = gv0[idx], vb = gv0[idx + 8];

    // ---- initial moments per system (8-lane reduction) ----
    float a, c, e;
    {
        a = xa.x * xa.x; a = fmaf(xa.y, xa.y, a); a = fmaf(xa.z, xa.z, a); a = fmaf(xa.w, xa.w, a);
        a = fmaf(xb.x, xb.x, a); a = fmaf(xb.y, xb.y, a); a = fmaf(xb.z, xb.z, a); a = fmaf(xb.w, xb.w, a);
        c = xa.x * va.x; c = fmaf(xa.y, va.y, c); c = fmaf(xa.z, va.z, c); c = fmaf(xa.w, va.w, c);
        c = fmaf(xb.x, vb.x, c); c = fmaf(xb.y, vb.y, c); c = fmaf(xb.z, vb.z, c); c = fmaf(xb.w, vb.w, c);
        e = va.x * va.x; e = fmaf(va.y, va.y, e); e = fmaf(va.z, va.z, e); e = fmaf(va.w, va.w, e);
        e = fmaf(vb.x, vb.x, e); e = fmaf(vb.y, vb.y, e); e = fmaf(vb.z, vb.z, e); e = fmaf(vb.w, vb.w, e);
        #pragma unroll
        for (int m = 1; m <= 4; m <<= 1) {          // within 8-lane system group
            a += __shfl_xor_sync(0xffffffffu, a, m);
            c += __shfl_xor_sync(0xffffffffu, c, m);
            e += __shfl_xor_sync(0xffffffffu, e, m);
        }
    }

    // ---- pack state: 8 dof/lane = 4 f32x2 each for X and V ----
    unsigned long long X01, X23, X45, X67, V01, V23, V45, V67;
    PACKAB(X01, xa.x, xa.y); PACKAB(X23, xa.z, xa.w);
    PACKAB(X45, xb.x, xb.y); PACKAB(X67, xb.z, xb.w);
    PACKAB(V01, va.x, va.y); PACKAB(V23, va.z, va.w);
    PACKAB(V45, vb.x, vb.y); PACKAB(V67, vb.z, vb.w);

    // ---- snapshot 0 ----
    const float4* px0 = out + idx;
    const float4* pv0 = out + (size_t)(NSTEP + 1) * F4SNAP + idx;
    STG128(px0, 0, X01, X23); STG128(px0, 128, X45, X67);
    STG128(pv0, 0, V01, V23); STG128(pv0, 128, V45, V67);

    // ---- main loop (bases at snapshot 1) ----
    if (kT == 1.0f && mass == 1.0f && Q == 1.0f)
        run_loop(1.0f, 1.0f, 1.0f, a, c, e,
                 X01, X23, X45, X67, V01, V23, V45, V67,
                 px0 + F4SNAP, pv0 + F4SNAP);
    else
        run_loop(kT, mass, Q, a, c, e,
                 X01, X23, X45, X67, V01, V23, V45, V67,
                 px0 + F4SNAP, pv0 + F4SNAP);
}

extern "C" void kernel_launch(void* const* d_in, const int* in_sizes, int n_in,
                              void* d_out, int out_size)
{
    const float4* x0   = (const float4*)d_in[0];
    const float4* v0   = (const float4*)d_in[1];
    const float*  kT   = (const float*)d_in[2];
    const float*  mass = (const float*)d_in[3];
    const float*  Q    = (const float*)d_in[4];
    float4* out = (float4*)d_out;

    // 1024 systems, 4/warp -> 256 warps; 128 blocks x 64 threads:
    // 2 warps/SM over 128 SMs (256 SMSPs, 1 warp each)
    nhc_kernel<<<128, 64>>>(x0, v0, kT, mass, Q, out);
}